// round 1
// baseline (speedup 1.0000x reference)
#include <cuda_runtime.h>
#include <math_constants.h>

#define Ssz   50
#define Hsz   256
#define NPT   3200
#define TILE  16
#define EROWS 32

// ---------------- scratch (static device globals; no allocation) ----------------
static __device__ float  g_enc_t[(size_t)9600 * Ssz * Hsz];   // 491.5 MB
static __device__ float4 g_wpack[512 * 256];                  // gate-interleaved [kk][k] -> (i,f,g,o)
static __device__ float4 g_bias4[256];                        // combined bias per k, 4 gates
static __device__ float4 g_w2pack[64 * 256];                  // W2T packed over h in float4
static __device__ float4 g_w1pack[64 * 256];                  // W1T packed over h in float4

// ---------------- fast activations (exp2-based, ~2ulp) ----------------
__device__ __forceinline__ float fsig(float x){
    return __fdividef(1.f, 1.f + __expf(-x));
}
__device__ __forceinline__ float ftanh(float x){
    return 1.f - __fdividef(2.f, 1.f + __expf(2.f * x));
}

// ---------------- weight packing ----------------
__global__ void pack_gates_kernel(const float* __restrict__ Wih, const float* __restrict__ Whh,
                                  const float* __restrict__ bih, const float* __restrict__ bhh){
    int kk = blockIdx.x, k = threadIdx.x;          // kk in [0,512): 0..255 -> x path, 256..511 -> h path
    const float* src = (kk < 256) ? Wih : Whh;
    int col = kk & 255;
    float4 v;
    v.x = src[(size_t)(k      ) * 256 + col];      // gate i row j=k
    v.y = src[(size_t)(k + 256) * 256 + col];      // gate f
    v.z = src[(size_t)(k + 512) * 256 + col];      // gate g
    v.w = src[(size_t)(k + 768) * 256 + col];      // gate o
    g_wpack[kk * 256 + k] = v;
    if (kk == 0){
        float4 b;
        b.x = bih[k]       + bhh[k];
        b.y = bih[k + 256] + bhh[k + 256];
        b.z = bih[k + 512] + bhh[k + 512];
        b.w = bih[k + 768] + bhh[k + 768];
        g_bias4[k] = b;
    }
}

__global__ void pack_w_kernel(const float* __restrict__ W2, const float* __restrict__ W1){
    int h4 = blockIdx.x, k = threadIdx.x;
    g_w2pack[h4 * 256 + k] = ((const float4*)(W2 + (size_t)k * 256))[h4];  // W2T[h..h+3][k]
    g_w1pack[h4 * 256 + k] = ((const float4*)(W1 + (size_t)k * 256))[h4];  // W1T[h..h+3][k]
}

// ---------------- enc_t = enc @ W1^T  (per-tensor [160000,256] x [256,256]) ----------------
__global__ __launch_bounds__(256, 2) void enc_t_kernel(const float* __restrict__ e0,
                                                       const float* __restrict__ e1,
                                                       const float* __restrict__ e2){
    __shared__ float4 in_s[EROWS * 64];            // 32 rows x 256 floats = 32 KB
    int b  = blockIdx.x;                           // 0..14999
    int t  = b / 5000;
    int rb = (b % 5000) * EROWS;
    const float* enc = (t == 0) ? e0 : ((t == 1) ? e1 : e2);
    const float4* src = (const float4*)(enc + (size_t)rb * Hsz);
    int k = threadIdx.x;
    for (int i = k; i < EROWS * 64; i += 256) in_s[i] = src[i];
    __syncthreads();

    float acc[EROWS];
#pragma unroll
    for (int r = 0; r < EROWS; r++) acc[r] = 0.f;

#pragma unroll 1
    for (int h4 = 0; h4 < 64; h4++){
        float4 w = g_w1pack[h4 * 256 + k];
#pragma unroll
        for (int r = 0; r < EROWS; r++){
            float4 v = in_s[r * 64 + h4];
            acc[r] = fmaf(v.w, w.w, fmaf(v.z, w.z, fmaf(v.y, w.y, fmaf(v.x, w.x, acc[r]))));
        }
    }
    float* dst = g_enc_t + ((size_t)t * 160000 + rb) * Hsz;
#pragma unroll
    for (int r = 0; r < EROWS; r++) dst[(size_t)r * Hsz + k] = acc[r];
}

// ---------------- recurrence: TILE rows per CTA, all 50 steps ----------------
__global__ __launch_bounds__(256, 2) void recur_kernel(const float* __restrict__ e0,
                                                       const float* __restrict__ e1,
                                                       const float* __restrict__ e2,
                                                       const float* __restrict__ vt,
                                                       float* __restrict__ out){
    __shared__ float in_cat[TILE][512];            // [r][0:256)=x (later dec), [256:512)=h
    __shared__ float u_s[TILE][52];
    __shared__ int   idx_s[TILE];
    __shared__ float vt_s[Hsz];

    const int tid  = threadIdx.x;                  // = k in [0,256)
    const int bid  = blockIdx.x;                   // 0..599, no tensor mixing (200 CTAs/tensor)
    const int t    = bid / 200;
    const int n0   = (bid % 200) * TILE;
    const int wid  = tid >> 5, lane = tid & 31;

    const float* enc  = (t == 0) ? e0 : ((t == 1) ? e1 : e2);
    const float* encb = enc + (size_t)n0 * (Ssz * Hsz);
    const float* etb  = g_enc_t + (size_t)bid * TILE * Ssz * Hsz;
    float* score_out  = out + (size_t)t * 8160000 + (size_t)n0 * 2500;
    float* idx_out    = out + (size_t)t * 8160000 + 8000000 + (size_t)n0 * 50;

    vt_s[tid] = vt[tid];

    // init: c = h0 = sum_s enc[row,s,:], x = 0
    float c[TILE];
#pragma unroll
    for (int r = 0; r < TILE; r++){
        float s = 0.f;
        const float* p = encb + (size_t)r * Ssz * Hsz + tid;
#pragma unroll 1
        for (int ss = 0; ss < Ssz; ss++) s += p[ss * Hsz];
        c[r] = s;
        in_cat[r][256 + tid] = s;
        in_cat[r][tid] = 0.f;
    }
    __syncthreads();

#pragma unroll 1
    for (int step = 0; step < Ssz; step++){
        // ---- Phase A: gates[r][4] = [x|h] @ Wcat^T ----
        float4 acc[TILE];
#pragma unroll
        for (int r = 0; r < TILE; r++) acc[r] = make_float4(0.f, 0.f, 0.f, 0.f);

#pragma unroll 1
        for (int kk4 = 0; kk4 < 128; kk4++){
            const float4* wp = g_wpack + (kk4 * 4) * 256 + tid;
            float4 w0 = wp[0];
            float4 w1 = wp[256];
            float4 w2 = wp[512];
            float4 w3 = wp[768];
#pragma unroll
            for (int r = 0; r < TILE; r++){
                float4 v = *(const float4*)(&in_cat[r][kk4 * 4]);
                acc[r].x = fmaf(v.x, w0.x, acc[r].x);
                acc[r].y = fmaf(v.x, w0.y, acc[r].y);
                acc[r].z = fmaf(v.x, w0.z, acc[r].z);
                acc[r].w = fmaf(v.x, w0.w, acc[r].w);
                acc[r].x = fmaf(v.y, w1.x, acc[r].x);
                acc[r].y = fmaf(v.y, w1.y, acc[r].y);
                acc[r].z = fmaf(v.y, w1.z, acc[r].z);
                acc[r].w = fmaf(v.y, w1.w, acc[r].w);
                acc[r].x = fmaf(v.z, w2.x, acc[r].x);
                acc[r].y = fmaf(v.z, w2.y, acc[r].y);
                acc[r].z = fmaf(v.z, w2.z, acc[r].z);
                acc[r].w = fmaf(v.z, w2.w, acc[r].w);
                acc[r].x = fmaf(v.w, w3.x, acc[r].x);
                acc[r].y = fmaf(v.w, w3.y, acc[r].y);
                acc[r].z = fmaf(v.w, w3.z, acc[r].z);
                acc[r].w = fmaf(v.w, w3.w, acc[r].w);
            }
        }
        __syncthreads();   // all reads of in_cat done before h is overwritten

        // ---- Phase B: LSTM cell (i,f,g,o), update c, write h ----
        {
            float4 bias = g_bias4[tid];
#pragma unroll
            for (int r = 0; r < TILE; r++){
                float gi = fsig (acc[r].x + bias.x);
                float gf = fsig (acc[r].y + bias.y);
                float gg = ftanh(acc[r].z + bias.z);
                float go = fsig (acc[r].w + bias.w);
                float cn = fmaf(gf, c[r], gi * gg);
                c[r] = cn;
                in_cat[r][256 + tid] = go * ftanh(cn);
            }
        }
        __syncthreads();   // h visible to everyone

        // ---- Phase C: dec[r][k] = h @ W2^T, stored into the (consumed) x slot ----
        {
            float dacc[TILE];
#pragma unroll
            for (int r = 0; r < TILE; r++) dacc[r] = 0.f;
#pragma unroll 1
            for (int h4 = 0; h4 < 64; h4++){
                float4 w = g_w2pack[h4 * 256 + tid];
#pragma unroll
                for (int r = 0; r < TILE; r++){
                    float4 v = *(const float4*)(&in_cat[r][256 + h4 * 4]);
                    dacc[r] = fmaf(v.w, w.w, fmaf(v.z, w.z, fmaf(v.y, w.y, fmaf(v.x, w.x, dacc[r]))));
                }
            }
#pragma unroll
            for (int r = 0; r < TILE; r++) in_cat[r][tid] = dacc[r];   // disjoint from h region
        }
        __syncthreads();   // dec visible

        // ---- Phase D: u[r][s] = sum_k tanh(enc_t + dec) * vt ----
#pragma unroll 1
        for (int task = wid; task < TILE * Ssz; task += 8){
            int r  = task / Ssz;
            int ss = task - r * Ssz;
            const float4* ep = (const float4*)(etb + ((size_t)r * Ssz + ss) * Hsz);
            float4 elo = ep[lane];
            float4 ehi = ep[32 + lane];
            float4 dlo = *(const float4*)(&in_cat[r][4 * lane]);
            float4 dhi = *(const float4*)(&in_cat[r][128 + 4 * lane]);
            float4 v0  = *(const float4*)(&vt_s[4 * lane]);
            float4 v1  = *(const float4*)(&vt_s[128 + 4 * lane]);
            float p0, p1;
            p0 = ftanh(elo.x + dlo.x) * v0.x;
            p1 = ftanh(elo.y + dlo.y) * v0.y;
            p0 = fmaf(ftanh(elo.z + dlo.z), v0.z, p0);
            p1 = fmaf(ftanh(elo.w + dlo.w), v0.w, p1);
            p0 = fmaf(ftanh(ehi.x + dhi.x), v1.x, p0);
            p1 = fmaf(ftanh(ehi.y + dhi.y), v1.y, p1);
            p0 = fmaf(ftanh(ehi.z + dhi.z), v1.z, p0);
            p1 = fmaf(ftanh(ehi.w + dhi.w), v1.w, p1);
            float p = p0 + p1;
#pragma unroll
            for (int off = 16; off; off >>= 1)
                p += __shfl_xor_sync(0xffffffffu, p, off);
            if (lane == 0) u_s[r][ss] = p;
        }
        __syncthreads();

        // ---- Phase E: softmax + argmax (first-max tiebreak), write outputs ----
#pragma unroll 1
        for (int rr = 0; rr < 2; rr++){
            int r = wid + rr * 8;
            float ua = u_s[r][lane];                                   // lane < 32 < 50 always valid
            float ub = (lane + 32 < Ssz) ? u_s[r][lane + 32] : -CUDART_INF_F;
            float bm = ua; int bi = lane;
            if (ub > bm){ bm = ub; bi = lane + 32; }
#pragma unroll
            for (int off = 16; off; off >>= 1){
                float vm = __shfl_xor_sync(0xffffffffu, bm, off);
                int   vi = __shfl_xor_sync(0xffffffffu, bi, off);
                if (vm > bm || (vm == bm && vi < bi)){ bm = vm; bi = vi; }
            }
            float ea = __expf(ua - bm);
            float eb = (lane + 32 < Ssz) ? __expf(ub - bm) : 0.f;
            float sm = ea + eb;
#pragma unroll
            for (int off = 16; off; off >>= 1)
                sm += __shfl_xor_sync(0xffffffffu, sm, off);
            float inv = 1.0f / sm;
            float* so = score_out + (size_t)r * 2500 + step * 50;
            so[lane] = ea * inv;
            if (lane + 32 < Ssz) so[lane + 32] = eb * inv;
            if (lane == 0){
                idx_s[r] = bi;
                idx_out[(size_t)r * 50 + step] = (float)bi;
            }
        }
        __syncthreads();

        // ---- Phase F: gather x_next = enc[row, idx, :] ----
#pragma unroll
        for (int r = 0; r < TILE; r++){
            int ii = idx_s[r];
            in_cat[r][tid] = encb[(size_t)r * Ssz * Hsz + (size_t)ii * Hsz + tid];
        }
        __syncthreads();
    }
}

// ---------------- launch ----------------
extern "C" void kernel_launch(void* const* d_in, const int* in_sizes, int n_in,
                              void* d_out, int out_size){
    const float* home = (const float*)d_in[0];
    const float* vis  = (const float*)d_in[1];
    const float* team = (const float*)d_in[2];
    const float* Wih  = (const float*)d_in[3];
    const float* Whh  = (const float*)d_in[4];
    const float* bih  = (const float*)d_in[5];
    const float* bhh  = (const float*)d_in[6];
    const float* W1   = (const float*)d_in[7];
    const float* W2   = (const float*)d_in[8];
    const float* vt   = (const float*)d_in[9];
    float* out = (float*)d_out;

    pack_gates_kernel<<<512, 256>>>(Wih, Whh, bih, bhh);
    pack_w_kernel<<<64, 256>>>(W2, W1);
    enc_t_kernel<<<15000, 256>>>(home, vis, team);
    recur_kernel<<<600, 256>>>(home, vis, team, vt, out);
}